// round 1
// baseline (speedup 1.0000x reference)
#include <cuda_runtime.h>
#include <cuda_bf16.h>

#define USER_NUM 100000
#define ITEM_NUM 50000
#define N_NODES  150000
#define EMB      128
#define N_EDGES  600000
#define NELEM    (N_NODES * EMB)      // 19,200,000 floats
#define NVEC     (NELEM / 4)          // 4,800,000 float4
#define UVEC     (USER_NUM * EMB / 4) // 3,200,000 float4

// Scratch: layer outputs live here (static device globals — allocation-guard safe).
__device__ float4 g_e0[NVEC];  // ego^(0) = concat(user, item)
__device__ float4 g_e1[NVEC];  // ego^(1)
__device__ float4 g_e2[NVEC];  // ego^(2)
__device__ float4 g_e3[NVEC];  // ego^(3)

// ---------------------------------------------------------------------------
// Init: ego0 = concat(user_emb, item_emb)
// ---------------------------------------------------------------------------
__global__ void k_init(const float4* __restrict__ u, const float4* __restrict__ it) {
    int i = blockIdx.x * blockDim.x + threadIdx.x;
    if (i >= NVEC) return;
    g_e0[i] = (i < UVEC) ? u[i] : it[i - UVEC];
}

// ---------------------------------------------------------------------------
// Zero a layer buffer (atomic scatter target must start at 0 every replay)
// ---------------------------------------------------------------------------
__global__ void k_zero(float4* __restrict__ dst) {
    int i = blockIdx.x * blockDim.x + threadIdx.x;
    if (i >= NVEC) return;
    dst[i] = make_float4(0.f, 0.f, 0.f, 0.f);
}

// ---------------------------------------------------------------------------
// SpMM (COO scatter): one warp per edge, 32 lanes x float4 = 128 features.
// dst[row] += val * src[col]  via vector RED (atomicAdd float4, sm_90+).
// ---------------------------------------------------------------------------
__global__ void k_spmm(const float* __restrict__ vals,
                       const int*   __restrict__ rows,
                       const int*   __restrict__ cols,
                       const float4* __restrict__ src,
                       float4* __restrict__ dst) {
    int t = blockIdx.x * blockDim.x + threadIdx.x;
    int e = t >> 5;
    if (e >= N_EDGES) return;
    int lane = t & 31;

    float v = vals[e];          // warp-uniform (broadcast)
    int   c = cols[e];
    int   r = rows[e];

    float4 x = src[c * 32 + lane];
    float4 y = make_float4(v * x.x, v * x.y, v * x.z, v * x.w);
    atomicAdd(&dst[r * 32 + lane], y);   // red.global.add.v4.f32
}

// ---------------------------------------------------------------------------
// Combine: out = (e1 + e2 + e3) / 3   (single pass; d_out is poisoned, write all)
// ---------------------------------------------------------------------------
__global__ void k_combine(float4* __restrict__ out) {
    int i = blockIdx.x * blockDim.x + threadIdx.x;
    if (i >= NVEC) return;
    float4 a = g_e1[i];
    float4 b = g_e2[i];
    float4 c = g_e3[i];
    const float s = 1.0f / 3.0f;
    out[i] = make_float4((a.x + b.x + c.x) * s,
                         (a.y + b.y + c.y) * s,
                         (a.z + b.z + c.z) * s,
                         (a.w + b.w + c.w) * s);
}

// ---------------------------------------------------------------------------
// Launch
// Inputs (metadata order): 0=user_emb f32, 1=item_emb f32, 2=edge_vals f32,
//                          3=edge_row i32, 4=edge_col i32
// Output: 19.2M floats = concat(user_all, item_all)
// ---------------------------------------------------------------------------
extern "C" void kernel_launch(void* const* d_in, const int* in_sizes, int n_in,
                              void* d_out, int out_size) {
    const float4* u    = (const float4*)d_in[0];
    const float4* it   = (const float4*)d_in[1];
    const float*  vals = (const float*) d_in[2];
    const int*    rows = (const int*)   d_in[3];
    const int*    cols = (const int*)   d_in[4];
    float4* out = (float4*)d_out;

    float4* e0; cudaGetSymbolAddress((void**)&e0, g_e0);
    float4* e1; cudaGetSymbolAddress((void**)&e1, g_e1);
    float4* e2; cudaGetSymbolAddress((void**)&e2, g_e2);
    float4* e3; cudaGetSymbolAddress((void**)&e3, g_e3);

    const int TPB = 256;
    const int vec_blocks  = (NVEC + TPB - 1) / TPB;            // 18750
    const int spmm_blocks = (N_EDGES * 32 + TPB - 1) / TPB;    // 75000

    k_init<<<vec_blocks, TPB>>>(u, it);

    k_zero<<<vec_blocks, TPB>>>(e1);
    k_spmm<<<spmm_blocks, TPB>>>(vals, rows, cols, e0, e1);

    k_zero<<<vec_blocks, TPB>>>(e2);
    k_spmm<<<spmm_blocks, TPB>>>(vals, rows, cols, e1, e2);

    k_zero<<<vec_blocks, TPB>>>(e3);
    k_spmm<<<spmm_blocks, TPB>>>(vals, rows, cols, e2, e3);

    k_combine<<<vec_blocks, TPB>>>(out);
}

// round 2
// speedup vs baseline: 1.7582x; 1.7582x over previous
#include <cuda_runtime.h>
#include <cuda_bf16.h>

#define USER_NUM 100000
#define ITEM_NUM 50000
#define N_NODES  150000
#define EMB      128
#define N_EDGES  600000
#define NVEC     (N_NODES * EMB / 4)   // 4,800,000 float4

#define SCAN_B   1024
#define NB_SCAN  ((N_NODES + SCAN_B - 1) / SCAN_B)   // 147

// ---- static device scratch (allocation-guard safe) ----
__device__ float4 g_e1[NVEC];
__device__ float4 g_e2[NVEC];
__device__ int    g_count[N_NODES];
__device__ int    g_start[N_NODES];
__device__ int    g_cursor[N_NODES];
__device__ int    g_bsum[NB_SCAN];
__device__ int    g_scol[N_EDGES];
__device__ float  g_sval[N_EDGES];

// ---------------------------------------------------------------------------
// CSR build: histogram -> exclusive scan -> scatter (counting sort by row)
// ---------------------------------------------------------------------------
__global__ void k_hist(const int* __restrict__ rows) {
    int e = blockIdx.x * blockDim.x + threadIdx.x;
    if (e < N_EDGES) atomicAdd(&g_count[rows[e]], 1);
}

// Block-local exclusive scan (Hillis-Steele, 1024/block), emits block sums.
__global__ void k_scan1() {
    __shared__ int s[SCAN_B];
    int tid = threadIdx.x;
    int i = blockIdx.x * SCAN_B + tid;
    int x = (i < N_NODES) ? g_count[i] : 0;
    s[tid] = x;
    __syncthreads();
    #pragma unroll
    for (int off = 1; off < SCAN_B; off <<= 1) {
        int t = (tid >= off) ? s[tid - off] : 0;
        __syncthreads();
        s[tid] += t;
        __syncthreads();
    }
    if (i < N_NODES) g_start[i] = s[tid] - x;      // exclusive
    if (tid == SCAN_B - 1) g_bsum[blockIdx.x] = s[tid];
}

// Scan the 147 block sums in one block.
__global__ void k_scan2() {
    __shared__ int s[256];
    int tid = threadIdx.x;
    int x = (tid < NB_SCAN) ? g_bsum[tid] : 0;
    s[tid] = x;
    __syncthreads();
    #pragma unroll
    for (int off = 1; off < 256; off <<= 1) {
        int t = (tid >= off) ? s[tid - off] : 0;
        __syncthreads();
        s[tid] += t;
        __syncthreads();
    }
    if (tid < NB_SCAN) g_bsum[tid] = s[tid] - x;   // exclusive
}

// Add block offsets; init scatter cursors.
__global__ void k_scan3() {
    int i = blockIdx.x * SCAN_B + threadIdx.x;
    if (i >= N_NODES) return;
    int st = g_start[i] + g_bsum[blockIdx.x];
    g_start[i]  = st;
    g_cursor[i] = st;
}

// Scatter (val, col) into row-sorted order.
__global__ void k_build(const float* __restrict__ vals,
                        const int*   __restrict__ rows,
                        const int*   __restrict__ cols) {
    int e = blockIdx.x * blockDim.x + threadIdx.x;
    if (e >= N_EDGES) return;
    int pos = atomicAdd(&g_cursor[rows[e]], 1);
    g_scol[pos] = cols[e];
    g_sval[pos] = vals[e];
}

// ---------------------------------------------------------------------------
// CSR SpMM gather: one warp per row; 32 lanes x float4 = 128 features.
// ---------------------------------------------------------------------------
__global__ void k_gather_first(const float4* __restrict__ u,
                               const float4* __restrict__ it,
                               float4* __restrict__ dst) {
    int t = blockIdx.x * blockDim.x + threadIdx.x;
    int row = t >> 5;
    if (row >= N_NODES) return;
    int lane = t & 31;
    int s = g_start[row], n = g_count[row];
    float4 acc = make_float4(0.f, 0.f, 0.f, 0.f);
    for (int j = s; j < s + n; ++j) {
        int   c = g_scol[j];
        float v = g_sval[j];
        const float4* base = (c < USER_NUM) ? (u + c * 32)
                                            : (it + (c - USER_NUM) * 32);
        float4 x = base[lane];
        acc.x += v * x.x; acc.y += v * x.y; acc.z += v * x.z; acc.w += v * x.w;
    }
    dst[row * 32 + lane] = acc;
}

__global__ void k_gather_mid(const float4* __restrict__ src,
                             float4* __restrict__ dst) {
    int t = blockIdx.x * blockDim.x + threadIdx.x;
    int row = t >> 5;
    if (row >= N_NODES) return;
    int lane = t & 31;
    int s = g_start[row], n = g_count[row];
    float4 acc = make_float4(0.f, 0.f, 0.f, 0.f);
    #pragma unroll 4
    for (int j = s; j < s + n; ++j) {
        int   c = g_scol[j];
        float v = g_sval[j];
        float4 x = src[c * 32 + lane];
        acc.x += v * x.x; acc.y += v * x.y; acc.z += v * x.z; acc.w += v * x.w;
    }
    dst[row * 32 + lane] = acc;
}

// Last layer fused with combine: out = (e1 + e2 + spmm(e2)) / 3
__global__ void k_gather_last(const float4* __restrict__ src,
                              float4* __restrict__ out) {
    int t = blockIdx.x * blockDim.x + threadIdx.x;
    int row = t >> 5;
    if (row >= N_NODES) return;
    int lane = t & 31;
    int s = g_start[row], n = g_count[row];
    float4 acc = make_float4(0.f, 0.f, 0.f, 0.f);
    #pragma unroll 4
    for (int j = s; j < s + n; ++j) {
        int   c = g_scol[j];
        float v = g_sval[j];
        float4 x = src[c * 32 + lane];
        acc.x += v * x.x; acc.y += v * x.y; acc.z += v * x.z; acc.w += v * x.w;
    }
    int idx = row * 32 + lane;
    float4 a = g_e1[idx];
    float4 b = g_e2[idx];
    const float sc = 1.0f / 3.0f;
    out[idx] = make_float4((a.x + b.x + acc.x) * sc,
                           (a.y + b.y + acc.y) * sc,
                           (a.z + b.z + acc.z) * sc,
                           (a.w + b.w + acc.w) * sc);
}

// ---------------------------------------------------------------------------
// Launch. Inputs: 0=user_emb f32, 1=item_emb f32, 2=edge_vals f32,
//                 3=edge_row i32, 4=edge_col i32.  Output: 19.2M f32.
// ---------------------------------------------------------------------------
extern "C" void kernel_launch(void* const* d_in, const int* in_sizes, int n_in,
                              void* d_out, int out_size) {
    const float4* u    = (const float4*)d_in[0];
    const float4* it   = (const float4*)d_in[1];
    const float*  vals = (const float*) d_in[2];
    const int*    rows = (const int*)   d_in[3];
    const int*    cols = (const int*)   d_in[4];
    float4* out = (float4*)d_out;

    float4* e1;  cudaGetSymbolAddress((void**)&e1, g_e1);
    float4* e2;  cudaGetSymbolAddress((void**)&e2, g_e2);
    int* cnt;    cudaGetSymbolAddress((void**)&cnt, g_count);

    const int TPB = 256;
    const int edge_blocks = (N_EDGES + TPB - 1) / TPB;          // 2344
    const int row_blocks  = (N_NODES * 32 + TPB - 1) / TPB;     // 18750

    // --- CSR build ---
    cudaMemsetAsync(cnt, 0, N_NODES * sizeof(int));
    k_hist <<<edge_blocks, TPB>>>(rows);
    k_scan1<<<NB_SCAN, SCAN_B>>>();
    k_scan2<<<1, 256>>>();
    k_scan3<<<NB_SCAN, SCAN_B>>>();
    k_build<<<edge_blocks, TPB>>>(vals, rows, cols);

    // --- 3 SpMM layers (endpoints fused) ---
    k_gather_first<<<row_blocks, TPB>>>(u, it, e1);
    k_gather_mid  <<<row_blocks, TPB>>>(e1, e2);
    k_gather_last <<<row_blocks, TPB>>>(e2, out);
}